// round 15
// baseline (speedup 1.0000x reference)
#include <cuda_runtime.h>
#include <cuda_fp16.h>
#include <math.h>
#include <stdint.h>

#define NTOK 4096
#define DIM  1024
#define FDIM 4096
#define NEXP 8
#define KSPLIT 4

// ---------------- scratch (static device globals; no allocation allowed) ----
__device__ float g_sn[NEXP * DIM];
__device__ float g_M[NEXP * DIM];            // fp32-exact gate numerator matrix
__device__ float g_norm2[NTOK];
__device__ int   g_topi[NTOK * 2];
__device__ float g_topw[NTOK * 2];
__device__ int   g_count[NEXP];
__device__ int   g_toklist[NEXP * NTOK];
__device__ float g_tokw[NEXP * NTOK];
// fp16 operands
__device__ __half g_xh[(size_t)NTOK * DIM];             // 8 MB
__device__ __half g_Wph[(size_t)DIM * DIM];             // 2 MB   [n][k]
__device__ __half g_W1h[(size_t)NEXP * FDIM * DIM];     // 64 MB  [e][F][k]  (transposed)
__device__ __half g_W2h[(size_t)NEXP * DIM * FDIM];     // 64 MB  [e][d][F]  (transposed)
__device__ __half g_Hh[(size_t)NEXP * NTOK * FDIM];     // 256 MB [e][m][F]

// ---------------- helpers ---------------------------------------------------
__device__ __forceinline__ uint32_t smem_u32(const void* p) {
    uint32_t a;
    asm("{ .reg .u64 t; cvta.to.shared.u64 t, %1; cvt.u32.u64 %0, t; }" : "=r"(a) : "l"(p));
    return a;
}
__device__ __forceinline__ void cp16(uint32_t dst, const void* src) {
    asm volatile("cp.async.cg.shared.global [%0], [%1], 16;" :: "r"(dst), "l"(src) : "memory");
}
__device__ __forceinline__ void cp_commit() {
    asm volatile("cp.async.commit_group;" ::: "memory");
}
__device__ __forceinline__ void cp_wait1() {
    asm volatile("cp.async.wait_group 1;" ::: "memory");
}
__device__ __forceinline__ void ldm_x4(uint32_t* r, uint32_t addr) {
    asm volatile("ldmatrix.sync.aligned.m8n8.x4.shared.b16 {%0,%1,%2,%3}, [%4];"
                 : "=r"(r[0]), "=r"(r[1]), "=r"(r[2]), "=r"(r[3]) : "r"(addr));
}
__device__ __forceinline__ void mma_f16(float* d, const uint32_t* a, const uint32_t* b) {
    asm volatile(
        "mma.sync.aligned.m16n8k16.row.col.f32.f16.f16.f32 "
        "{%0,%1,%2,%3}, {%4,%5,%6,%7}, {%8,%9}, {%0,%1,%2,%3};"
        : "+f"(d[0]), "+f"(d[1]), "+f"(d[2]), "+f"(d[3])
        : "r"(a[0]), "r"(a[1]), "r"(a[2]), "r"(a[3]), "r"(b[0]), "r"(b[1]));
}
__device__ __forceinline__ float gelu_exact(float v) {
    return 0.5f * v * (1.0f + erff(v * 0.70710678118654752440f));
}

// ---------------------------------------------------------------------------
__global__ void zero_kernel(float* __restrict__ out) {
    size_t i = (size_t)blockIdx.x * blockDim.x + threadIdx.x;
    if (i < (size_t)NTOK * DIM) out[i] = 0.0f;
    if (i < NTOK) g_norm2[i] = 0.0f;
    if (i < NEXP) g_count[i] = 0;
}

// fp32 -> fp16 elementwise (half2 granularity)
__global__ void cvth_kernel(const float* __restrict__ src, __half* __restrict__ dst, int n2) {
    int i = blockIdx.x * blockDim.x + threadIdx.x;
    if (i < n2) {
        float2 v = ((const float2*)src)[i];
        ((__half2*)dst)[i] = __floats2half2_rn(v.x, v.y);
    }
}

// src [e][Kd][Fd] fp32 -> dst [e][Fd][Kd] fp16  (tiled transpose)
__global__ void transp_kernel(const float* __restrict__ src, __half* __restrict__ dst,
                              int Kd, int Fd) {
    __shared__ float t[32][33];
    int e = blockIdx.z;
    const float* S = src + (size_t)e * Kd * Fd;
    __half* D = dst + (size_t)e * Kd * Fd;
    int f0 = blockIdx.x * 32, k0 = blockIdx.y * 32;
    int tx = threadIdx.x, ty = threadIdx.y;
    #pragma unroll
    for (int i = ty; i < 32; i += 8)
        t[i][tx] = S[(size_t)(k0 + i) * Fd + f0 + tx];
    __syncthreads();
    #pragma unroll
    for (int i = ty; i < 32; i += 8)
        D[(size_t)(f0 + i) * Kd + k0 + tx] = __float2half_rn(t[tx][i]);
}

__global__ void normsim_kernel(const float* __restrict__ sim) {
    int w = threadIdx.x >> 5, lane = threadIdx.x & 31;
    if (w >= NEXP) return;
    float ss = 0.0f;
    for (int k = lane; k < DIM; k += 32) { float v = sim[w * DIM + k]; ss += v * v; }
    #pragma unroll
    for (int off = 16; off; off >>= 1) ss += __shfl_xor_sync(0xffffffffu, ss, off);
    float inv = 1.0f / fmaxf(sqrtf(ss), 1e-12f);
    for (int k = lane; k < DIM; k += 32) g_sn[w * DIM + k] = sim[w * DIM + k] * inv;
}

// M[e][i] = sum_o Wp[o][i] * sn[e][o]   (fp32-exact gate numerators)
__global__ void gateM_kernel(const float* __restrict__ Wp) {
    int e = blockIdx.x;
    int i0 = threadIdx.x * 4;
    float4 acc = make_float4(0, 0, 0, 0);
    #pragma unroll 4
    for (int o = 0; o < DIM; o++) {
        float s = g_sn[e * DIM + o];
        float4 w = *(const float4*)(Wp + (size_t)o * DIM + i0);
        acc.x += s * w.x; acc.y += s * w.y; acc.z += s * w.z; acc.w += s * w.w;
    }
    *(float4*)(g_M + e * DIM + i0) = acc;
}

// one warp per token: fp32 dots x.M_e; |p| from fp16 norm (scale only); top2+softmax
__global__ void gate2_kernel(const float* __restrict__ x, const float* __restrict__ temp) {
    __shared__ float sM[NEXP][DIM];
    int tid = threadIdx.x;
    for (int i = tid; i < NEXP * DIM; i += 256) ((float*)sM)[i] = g_M[i];
    __syncthreads();
    int w = tid >> 5, lane = tid & 31;
    int t = blockIdx.x * 8 + w;
    const float4* xr = (const float4*)(x + (size_t)t * DIM);
    float acc[NEXP];
    #pragma unroll
    for (int e = 0; e < NEXP; e++) acc[e] = 0.0f;
    for (int k4 = lane; k4 < DIM / 4; k4 += 32) {
        float4 xv = xr[k4];
        #pragma unroll
        for (int e = 0; e < NEXP; e++) {
            float4 mv = *(const float4*)&sM[e][k4 * 4];
            acc[e] += xv.x * mv.x + xv.y * mv.y + xv.z * mv.z + xv.w * mv.w;
        }
    }
    #pragma unroll
    for (int off = 16; off; off >>= 1)
        #pragma unroll
        for (int e = 0; e < NEXP; e++) acc[e] += __shfl_xor_sync(0xffffffffu, acc[e], off);
    if (lane == 0) {
        float pn   = sqrtf(g_norm2[t]);
        float inv  = 1.0f / fmaxf(pn, 1e-12f);
        float tinv = 1.0f / temp[0];
        float sc[NEXP];
        #pragma unroll
        for (int e = 0; e < NEXP; e++) sc[e] = acc[e] * inv * tinv;
        int i0 = 0; float v0 = sc[0];
        #pragma unroll
        for (int e = 1; e < NEXP; e++) if (sc[e] > v0) { v0 = sc[e]; i0 = e; }
        int i1 = -1; float v1 = -1e30f;
        #pragma unroll
        for (int e = 0; e < NEXP; e++) if (e != i0 && sc[e] > v1) { v1 = sc[e]; i1 = e; }
        float e1 = expf(v1 - v0);
        float w0 = 1.0f / (1.0f + e1);
        g_topi[t * 2] = i0;  g_topi[t * 2 + 1] = i1;
        g_topw[t * 2] = w0;  g_topw[t * 2 + 1] = e1 * w0;
    }
}

__global__ void route_kernel() {
    int t = blockIdx.x * blockDim.x + threadIdx.x;
    if (t >= NTOK) return;
    #pragma unroll
    for (int k = 0; k < 2; k++) {
        int e = g_topi[t * 2 + k];
        int pos = atomicAdd(&g_count[e], 1);
        g_toklist[e * NTOK + pos] = t;
        g_tokw[e * NTOK + pos]    = g_topw[t * 2 + k];
    }
}

// ---------------------------------------------------------------------------
// fp16 m16n8k16 GEMM with ldmatrix fragment loads.
// CTA tile 256(tokens) x 128(features) x 64, 8 warps (4R x 2C), warp 64x64,
// cp.async 3-stage ring, one sync per chunk.
// MODE 0: A=xh[m][k],        B=Wph[n][k]    -> row-norm^2 (atomicAdd)
// MODE 1: A=xh[gather m][k], B=W1h[e][F][k] -> Hh[e][m][F] = f16(gelu(.+b1))
// MODE 2: A=Hh[e][m][F],     B=W2h[e][d][F] -> out[tok][d] += wv*(.+b2)
//         split-K: blockIdx.z = e*KSPLIT + split, each split covers FDIM/KSPLIT;
//         bias added only by split 0 (epilogue is atomicAdd, so splits compose).
// ---------------------------------------------------------------------------
template<int MODE>
__global__ __launch_bounds__(256)
void moe_hmma(const __half* __restrict__ Ab, const __half* __restrict__ Bb,
              const float* __restrict__ bias, float* __restrict__ out) {
    constexpr int K  = (MODE == 2) ? (FDIM / KSPLIT) : DIM;   // K range per CTA
    constexpr int NB = (MODE == 1) ? FDIM : DIM;   // bias row length
    constexpr int RS = 72;                          // smem row stride (halfs)
    constexpr int A_H = 256 * RS;                   // halfs per A stage
    constexpr int B_H = 128 * RS;
    constexpr int STAGE_H = A_H + B_H;

    extern __shared__ char smraw[];
    float* sBias = (float*)smraw;                   // 128 floats
    __half* smh = (__half*)(smraw + 1024);
    const uint32_t smb = smem_u32(smh);

    const int tid  = threadIdx.x;
    const int lane = tid & 31;
    const int wid  = tid >> 5;
    const int gid  = lane >> 2;
    const int tig  = lane & 3;
    const int R_warp = (wid & 3) * 64;
    const int C_warp = (wid >> 2) * 64;
    const int e     = (MODE == 2) ? (blockIdx.z / KSPLIT) : blockIdx.z;
    const int split = (MODE == 2) ? (blockIdx.z % KSPLIT) : 0;
    const int kbase = (MODE == 2) ? split * (FDIM / KSPLIT) : 0;

    const int R0 = blockIdx.y * 256;
    const int C0 = blockIdx.x * 128;
    int M = NTOK;
    if (MODE != 0) {
        M = g_count[e];
        if (R0 >= M) return;
        if (tid < 128) sBias[tid] = bias[(size_t)e * NB + C0 + tid];
    }

    // ---- A copy: 8 rows/thread (row = tid>>3 + 32i), 16B seg (tid&7) ----
    const int arow  = tid >> 3;
    const int akoff = (tid & 7) * 8;                // halfs
    const __half* aP[8];
    uint32_t aDst[8];
    #pragma unroll
    for (int i = 0; i < 8; i++) {
        int r = arow + 32 * i;
        if (MODE == 0) {
            aP[i] = Ab + (size_t)(R0 + r) * DIM + akoff;
        } else if (MODE == 1) {
            int gm = R0 + r;
            int gr = (gm < M) ? g_toklist[e * NTOK + gm] : 0;
            aP[i] = Ab + (size_t)gr * DIM + akoff;
        } else {
            aP[i] = g_Hh + ((size_t)e * NTOK + R0 + r) * FDIM + kbase + akoff;
        }
        aDst[i] = (uint32_t)((r * RS + akoff) * 2);
    }
    // ---- B copy: row = tid>>1, 2 x 16B segs ----
    const int brow  = tid >> 1;
    const int bkoff = (tid & 1) * 32;               // halfs
    const __half* bP;
    if (MODE == 0)      bP = Bb + (size_t)(C0 + brow) * DIM + bkoff;
    else if (MODE == 1) bP = Bb + (size_t)e * FDIM * DIM + (size_t)(C0 + brow) * DIM + bkoff;
    else                bP = Bb + (size_t)e * DIM * FDIM + (size_t)(C0 + brow) * FDIM + kbase + bkoff;
    const uint32_t bDst = (uint32_t)((A_H + brow * RS + bkoff) * 2);

    auto issue = [&](int c, int s) {
        uint32_t sb = smb + (uint32_t)(s * STAGE_H * 2);
        int k0 = c * 64;
        #pragma unroll
        for (int i = 0; i < 8; i++) cp16(sb + aDst[i], aP[i] + k0);
        #pragma unroll
        for (int i = 0; i < 4; i++) cp16(sb + bDst + i * 16, bP + k0 + i * 8);
    };

    // ---- ldmatrix lane addressing (byte offsets within a stage) ----
    const int l7  = lane & 7;
    const int l8  = (lane >> 3) & 1;
    const int l16 = (lane >> 4) & 1;
    uint32_t aLd[4], bLd[4];
    #pragma unroll
    for (int rt = 0; rt < 4; rt++)
        aLd[rt] = (uint32_t)(((R_warp + rt * 16 + l7 + l8 * 8) * RS + l16 * 8) * 2);
    #pragma unroll
    for (int cp = 0; cp < 4; cp++)
        bLd[cp] = (uint32_t)((A_H + (C_warp + cp * 16 + l7 + l16 * 8) * RS + l8 * 8) * 2);

    float acc[4][8][4];
    #pragma unroll
    for (int i = 0; i < 4; i++)
        #pragma unroll
        for (int j = 0; j < 8; j++)
            #pragma unroll
            for (int q = 0; q < 4; q++) acc[i][j][q] = 0.0f;

    constexpr int nch = K / 64;
    issue(0, 0); cp_commit();
    issue(1, 1); cp_commit();

    for (int c = 0; c < nch; ++c) {
        cp_wait1();
        __syncthreads();
        if (c + 2 < nch) issue(c + 2, (c + 2) % 3);
        cp_commit();

        const uint32_t stb = smb + (uint32_t)((c % 3) * STAGE_H * 2);
        #pragma unroll
        for (int kb = 0; kb < 4; kb++) {
            const uint32_t kbo = kb * 32;           // 16 halfs = 32 bytes
            uint32_t af[4][4];
            #pragma unroll
            for (int rt = 0; rt < 4; rt++)
                ldm_x4(af[rt], stb + aLd[rt] + kbo);
            uint32_t bf[8][2];
            #pragma unroll
            for (int cp = 0; cp < 4; cp++) {
                uint32_t r[4];
                ldm_x4(r, stb + bLd[cp] + kbo);
                bf[2 * cp][0] = r[0];     bf[2 * cp][1] = r[1];
                bf[2 * cp + 1][0] = r[2]; bf[2 * cp + 1][1] = r[3];
            }
            #pragma unroll
            for (int ct = 0; ct < 8; ct++)
                #pragma unroll
                for (int rt = 0; rt < 4; rt++)
                    mma_f16(acc[rt][ct], af[rt], bf[ct]);
        }
        // single sync per chunk; next top sync orders ring reuse
    }

    // ---- epilogue (D frag: [0]=(r,c) [1]=(r,c+1) [2]=(r+8,c) [3]=(r+8,c+1)) ----
    if (MODE == 0) {
        #pragma unroll
        for (int rt = 0; rt < 4; rt++) {
            float s0 = 0.0f, s1 = 0.0f;
            #pragma unroll
            for (int ct = 0; ct < 8; ct++) {
                s0 += acc[rt][ct][0] * acc[rt][ct][0] + acc[rt][ct][1] * acc[rt][ct][1];
                s1 += acc[rt][ct][2] * acc[rt][ct][2] + acc[rt][ct][3] * acc[rt][ct][3];
            }
            s0 += __shfl_xor_sync(0xffffffffu, s0, 1);
            s0 += __shfl_xor_sync(0xffffffffu, s0, 2);
            s1 += __shfl_xor_sync(0xffffffffu, s1, 1);
            s1 += __shfl_xor_sync(0xffffffffu, s1, 2);
            if (tig == 0) {
                int r = R0 + R_warp + rt * 16 + gid;
                atomicAdd(&g_norm2[r], s0);
                atomicAdd(&g_norm2[r + 8], s1);
            }
        }
    } else if (MODE == 1) {
        #pragma unroll
        for (int rt = 0; rt < 4; rt++) {
            int m = R0 + R_warp + rt * 16 + gid;
            __half* h0 = g_Hh + ((size_t)e * NTOK + m) * FDIM + C0;
            __half* h1 = h0 + (size_t)8 * FDIM;
            #pragma unroll
            for (int ct = 0; ct < 8; ct++) {
                int cl = C_warp + ct * 8 + 2 * tig;
                float b0 = sBias[cl], b1v = sBias[cl + 1];
                if (m < M)
                    *(__half2*)(h0 + cl) = __floats2half2_rn(
                        gelu_exact(acc[rt][ct][0] + b0), gelu_exact(acc[rt][ct][1] + b1v));
                if (m + 8 < M)
                    *(__half2*)(h1 + cl) = __floats2half2_rn(
                        gelu_exact(acc[rt][ct][2] + b0), gelu_exact(acc[rt][ct][3] + b1v));
            }
        }
    } else {
        const float bscale = (split == 0) ? 1.0f : 0.0f;
        #pragma unroll
        for (int rt = 0; rt < 4; rt++) {
            int m = R0 + R_warp + rt * 16 + gid;
            bool v0 = m < M, v1 = (m + 8) < M;
            int tok0 = 0, tok1 = 0; float wv0 = 0.f, wv1 = 0.f;
            if (v0) { tok0 = g_toklist[e * NTOK + m];     wv0 = g_tokw[e * NTOK + m]; }
            if (v1) { tok1 = g_toklist[e * NTOK + m + 8]; wv1 = g_tokw[e * NTOK + m + 8]; }
            #pragma unroll
            for (int ct = 0; ct < 8; ct++) {
                int cl = C_warp + ct * 8 + 2 * tig;
                int d  = C0 + cl;
                float b0 = bscale * sBias[cl], b1v = bscale * sBias[cl + 1];
                if (v0) {
                    float* o = out + (size_t)tok0 * DIM + d;
                    atomicAdd(&o[0], wv0 * (acc[rt][ct][0] + b0));
                    atomicAdd(&o[1], wv0 * (acc[rt][ct][1] + b1v));
                }
                if (v1) {
                    float* o = out + (size_t)tok1 * DIM + d;
                    atomicAdd(&o[0], wv1 * (acc[rt][ct][2] + b0));
                    atomicAdd(&o[1], wv1 * (acc[rt][ct][3] + b1v));
                }
            }
        }
    }
}

// ---------------------------------------------------------------------------
extern "C" void kernel_launch(void* const* d_in, const int* in_sizes, int n_in,
                              void* d_out, int out_size) {
    const float* x    = (const float*)d_in[0];
    const float* Wp   = (const float*)d_in[1];
    const float* sim  = (const float*)d_in[2];
    const float* temp = (const float*)d_in[3];
    const float* W1   = (const float*)d_in[4];
    const float* b1   = (const float*)d_in[5];
    const float* W2   = (const float*)d_in[6];
    const float* b2   = (const float*)d_in[7];
    float* out = (float*)d_out;

    const int smem = 1024 + 3 * (256 * 72 + 128 * 72) * 2;   // 166912
    cudaFuncSetAttribute(moe_hmma<0>, cudaFuncAttributeMaxDynamicSharedMemorySize, smem);
    cudaFuncSetAttribute(moe_hmma<1>, cudaFuncAttributeMaxDynamicSharedMemorySize, smem);
    cudaFuncSetAttribute(moe_hmma<2>, cudaFuncAttributeMaxDynamicSharedMemorySize, smem);

    __half* d_xh;  cudaGetSymbolAddress((void**)&d_xh,  g_xh);
    __half* d_wph; cudaGetSymbolAddress((void**)&d_wph, g_Wph);
    __half* d_w1h; cudaGetSymbolAddress((void**)&d_w1h, g_W1h);
    __half* d_w2h; cudaGetSymbolAddress((void**)&d_w2h, g_W2h);

    zero_kernel<<<(NTOK * DIM + 255) / 256, 256>>>(out);
    normsim_kernel<<<1, 256>>>(sim);
    gateM_kernel<<<NEXP, 256>>>(Wp);

    // operand conversion (one-time per launch)
    cvth_kernel<<<(NTOK * DIM / 2 + 255) / 256, 256>>>(x, d_xh, NTOK * DIM / 2);
    cvth_kernel<<<(DIM * DIM / 2 + 255) / 256, 256>>>(Wp, d_wph, DIM * DIM / 2);
    {
        dim3 b(32, 8);
        dim3 gt1(FDIM / 32, DIM / 32, NEXP);   // W1 [e][k=DIM][F=FDIM] -> [e][F][k]
        transp_kernel<<<gt1, b>>>(W1, d_w1h, DIM, FDIM);
        dim3 gt2(DIM / 32, FDIM / 32, NEXP);   // W2 [e][k=FDIM][d=DIM] -> [e][d][k]
        transp_kernel<<<gt2, b>>>(W2, d_w2h, FDIM, DIM);
    }

    dim3 g0(DIM / 128, NTOK / 256, 1);
    moe_hmma<0><<<g0, 256, smem>>>(d_xh, d_wph, nullptr, nullptr);

    gate2_kernel<<<NTOK / 8, 256>>>(x, temp);
    route_kernel<<<NTOK / 256, 256>>>();

    dim3 g1(FDIM / 128, NTOK / 256, NEXP);
    moe_hmma<1><<<g1, 256, smem>>>(d_xh, d_w1h, b1, nullptr);

    dim3 g2(DIM / 128, NTOK / 256, NEXP * KSPLIT);   // split-K over FDIM
    moe_hmma<2><<<g2, 256, smem>>>(nullptr, d_w2h, b2, out);
}